// round 1
// baseline (speedup 1.0000x reference)
#include <cuda_runtime.h>
#include <math.h>

namespace {
constexpr int NB = 72;      // batch = G * SAMPLE_NUMS
constexpr int SS = 512;
constexpr int HH = 768;
constexpr int NG = 8;
constexpr int SN = 9;
constexpr float TEMP_ = 0.07f;
constexpr float AVG_EPS_ = 1e-6f;
constexpr float COS_EPS_ = 1e-8f;
constexpr int VR = 2;
}

// Scratch (no allocations allowed)
__device__ float g_mask[3][NB * SS];   // mq, ma, mn
__device__ float g_msum[3][NB];
__device__ float g_self[3][NB * HH];
__device__ float g_alpha[3][NB * SS];
__device__ float g_cross[3][NB * HH];
__device__ float g_logits[3][NB];

// ---------------------------------------------------------------------------
// Kernel 1: per-batch masks, mask sums, self-averages; zero alpha.
// ---------------------------------------------------------------------------
__global__ void k1_prep(const float* __restrict__ x,
                        const float* __restrict__ am,
                        const int* __restrict__ qa) {
    const int b = blockIdx.x;
    const int tid = threadIdx.x;
    __shared__ float smq[SS], sma[SS], smn[SS];
    __shared__ float red[3][8];
    __shared__ float ssum[3];

    float pq = 0.f, pa = 0.f, pn = 0.f;
    for (int s = tid; s < SS; s += blockDim.x) {
        int q = qa[b * SS + s];
        float a = am[b * SS + s];
        float mq = (q == 1 || q == 2) ? a : 0.f;
        float ma = (q == 0 || q == 2) ? a : 0.f;
        float mn = (q == 3) ? a : 0.f;
        smq[s] = mq; sma[s] = ma; smn[s] = mn;
        g_mask[0][b * SS + s] = mq;
        g_mask[1][b * SS + s] = ma;
        g_mask[2][b * SS + s] = mn;
        g_alpha[0][b * SS + s] = 0.f;
        g_alpha[1][b * SS + s] = 0.f;
        g_alpha[2][b * SS + s] = 0.f;
        pq += mq; pa += ma; pn += mn;
    }
    #pragma unroll
    for (int o = 16; o > 0; o >>= 1) {
        pq += __shfl_down_sync(0xffffffffu, pq, o);
        pa += __shfl_down_sync(0xffffffffu, pa, o);
        pn += __shfl_down_sync(0xffffffffu, pn, o);
    }
    if ((tid & 31) == 0) {
        int w = tid >> 5;
        red[0][w] = pq; red[1][w] = pa; red[2][w] = pn;
    }
    __syncthreads();
    if (tid == 0) {
        float s0 = 0.f, s1 = 0.f, s2 = 0.f;
        for (int w = 0; w < 8; w++) { s0 += red[0][w]; s1 += red[1][w]; s2 += red[2][w]; }
        g_msum[0][b] = s0; g_msum[1][b] = s1; g_msum[2][b] = s2;
        ssum[0] = s0; ssum[1] = s1; ssum[2] = s2;
    }
    __syncthreads();

    const float* xb = x + (size_t)b * SS * HH;
    for (int h = tid; h < HH; h += blockDim.x) {
        float aq = 0.f, aa = 0.f, an = 0.f;
        for (int s = 0; s < SS; s++) {
            float v = xb[(size_t)s * HH + h];
            aq = fmaf(smq[s], v, aq);
            aa = fmaf(sma[s], v, aa);
            an = fmaf(smn[s], v, an);
        }
        g_self[0][b * HH + h] = aq / (ssum[0] + AVG_EPS_);
        g_self[1][b * HH + h] = aa / (ssum[1] + AVG_EPS_);
        g_self[2][b * HH + h] = an / (ssum[2] + AVG_EPS_);
    }
}

// ---------------------------------------------------------------------------
// Kernel 2: banded symmetric Gram + alpha accumulation.
// 64x64 tiles, upper triangle only (mirror contributions for off-diagonal).
// ---------------------------------------------------------------------------
__global__ void __launch_bounds__(256) k2_gram(const float* __restrict__ x,
                                               const int* __restrict__ turn) {
    const int b = blockIdx.z;
    const int I = blockIdx.y, J = blockIdx.x;
    if (J < I) return;
    const int s0 = I * 64, t0 = J * 64;
    const int* tb = turn + b * SS;
    // sorted turn ids + J>=I  =>  dt >= tb[t0]-tb[s0+63] for cross tiles
    if (tb[t0] - tb[s0 + 63] > VR) return;
    const bool diag = (I == J);
    const int tid = threadIdx.x;
    const int tx = tid & 15, ty = tid >> 4;

    __shared__ __align__(16) float As[32][68];
    __shared__ __align__(16) float Bs[32][68];
    __shared__ float sW[2][3][64];   // [side][wq/wa/wn][i]
    __shared__ float sM[2][3][64];   // [side][mq/ma/mn][i]
    __shared__ int   sT[2][64];
    __shared__ float accT[3][64];
    __shared__ float accS[3][64];

    if (tid < 128) {
        int side = tid >> 6, i = tid & 63;
        int tok = (side ? t0 : s0) + i;
        float mq = g_mask[0][b * SS + tok];
        float ma = g_mask[1][b * SS + tok];
        float mn = g_mask[2][b * SS + tok];
        sM[side][0][i] = mq; sM[side][1][i] = ma; sM[side][2][i] = mn;
        sW[side][0][i] = ma + mn;  // wq
        sW[side][1][i] = mq + mn;  // wa
        sW[side][2][i] = mq + ma;  // wn
        sT[side][i] = tb[tok];
    }
    if (tid < 64) {
        #pragma unroll
        for (int m = 0; m < 3; m++) { accT[m][tid] = 0.f; accS[m][tid] = 0.f; }
    }

    float acc[4][4];
    #pragma unroll
    for (int i = 0; i < 4; i++)
        #pragma unroll
        for (int j = 0; j < 4; j++) acc[i][j] = 0.f;

    const float4* xa = (const float4*)(x + ((size_t)b * SS + s0) * HH);
    const float4* xbp = (const float4*)(x + ((size_t)b * SS + t0) * HH);

    for (int k0 = 0; k0 < HH; k0 += 32) {
        __syncthreads();
        #pragma unroll
        for (int l = 0; l < 2; l++) {
            int idx = tid + l * 256;
            int i = idx >> 3, c4 = idx & 7;
            float4 va = xa[(size_t)i * (HH / 4) + (k0 >> 2) + c4];
            As[4 * c4 + 0][i] = va.x; As[4 * c4 + 1][i] = va.y;
            As[4 * c4 + 2][i] = va.z; As[4 * c4 + 3][i] = va.w;
            float4 vb = xbp[(size_t)i * (HH / 4) + (k0 >> 2) + c4];
            Bs[4 * c4 + 0][i] = vb.x; Bs[4 * c4 + 1][i] = vb.y;
            Bs[4 * c4 + 2][i] = vb.z; Bs[4 * c4 + 3][i] = vb.w;
        }
        __syncthreads();
        #pragma unroll
        for (int kk = 0; kk < 32; kk++) {
            float4 a  = *(const float4*)&As[kk][4 * ty];
            float4 bv = *(const float4*)&Bs[kk][4 * tx];
            acc[0][0] = fmaf(a.x, bv.x, acc[0][0]); acc[0][1] = fmaf(a.x, bv.y, acc[0][1]);
            acc[0][2] = fmaf(a.x, bv.z, acc[0][2]); acc[0][3] = fmaf(a.x, bv.w, acc[0][3]);
            acc[1][0] = fmaf(a.y, bv.x, acc[1][0]); acc[1][1] = fmaf(a.y, bv.y, acc[1][1]);
            acc[1][2] = fmaf(a.y, bv.z, acc[1][2]); acc[1][3] = fmaf(a.y, bv.w, acc[1][3]);
            acc[2][0] = fmaf(a.z, bv.x, acc[2][0]); acc[2][1] = fmaf(a.z, bv.y, acc[2][1]);
            acc[2][2] = fmaf(a.z, bv.z, acc[2][2]); acc[2][3] = fmaf(a.z, bv.w, acc[2][3]);
            acc[3][0] = fmaf(a.w, bv.x, acc[3][0]); acc[3][1] = fmaf(a.w, bv.y, acc[3][1]);
            acc[3][2] = fmaf(a.w, bv.z, acc[3][2]); acc[3][3] = fmaf(a.w, bv.w, acc[3][3]);
        }
    }

    // Contributions: alpha_q[t] += wq[s]*c(s,t)*band*d ; mirror for off-diag tiles.
    float cq[4], ca_[4], cn_[4], dq[4], da_[4], dn_[4];
    #pragma unroll
    for (int j = 0; j < 4; j++) { cq[j]=0.f; ca_[j]=0.f; cn_[j]=0.f; dq[j]=0.f; da_[j]=0.f; dn_[j]=0.f; }

    #pragma unroll
    for (int di = 0; di < 4; di++) {
        int sl = 4 * ty + di;
        int ts_ = sT[0][sl];
        float mqs = sM[0][0][sl], mas = sM[0][1][sl], mns = sM[0][2][sl];
        float wqs = sW[0][0][sl], was = sW[0][1][sl], wns = sW[0][2][sl];
        #pragma unroll
        for (int dj = 0; dj < 4; dj++) {
            int tl = 4 * tx + dj;
            int dt = sT[1][tl] - ts_;
            if (dt < -VR || dt > VR) continue;
            float wqt = sW[1][0][tl], wat = sW[1][1][tl], wnt = sW[1][2][tl];
            float coef = mqs * wqt + mas * wat + mns * wnt;  // symmetric c(s,t)
            float base = coef * acc[di][dj];
            cq[dj]  = fmaf(wqs, base, cq[dj]);
            ca_[dj] = fmaf(was, base, ca_[dj]);
            cn_[dj] = fmaf(wns, base, cn_[dj]);
            dq[di]  = fmaf(wqt, base, dq[di]);
            da_[di] = fmaf(wat, base, da_[di]);
            dn_[di] = fmaf(wnt, base, dn_[di]);
        }
    }
    #pragma unroll
    for (int dj = 0; dj < 4; dj++) {
        int tl = 4 * tx + dj;
        if (cq[dj]  != 0.f) atomicAdd(&accT[0][tl], cq[dj]);
        if (ca_[dj] != 0.f) atomicAdd(&accT[1][tl], ca_[dj]);
        if (cn_[dj] != 0.f) atomicAdd(&accT[2][tl], cn_[dj]);
    }
    if (!diag) {
        #pragma unroll
        for (int di = 0; di < 4; di++) {
            int sl = 4 * ty + di;
            if (dq[di]  != 0.f) atomicAdd(&accS[0][sl], dq[di]);
            if (da_[di] != 0.f) atomicAdd(&accS[1][sl], da_[di]);
            if (dn_[di] != 0.f) atomicAdd(&accS[2][sl], dn_[di]);
        }
    }
    __syncthreads();
    if (tid < 64) {
        #pragma unroll
        for (int m = 0; m < 3; m++) {
            float v = accT[m][tid];
            if (v != 0.f) atomicAdd(&g_alpha[m][b * SS + t0 + tid], v);
            if (!diag) {
                float w = accS[m][tid];
                if (w != 0.f) atomicAdd(&g_alpha[m][b * SS + s0 + tid], w);
            }
        }
    }
}

// ---------------------------------------------------------------------------
// Kernel 3: cross vectors  q_cross[h] = sum_t mq[t]*alpha_q[t]*x[t,h] / denom
// ---------------------------------------------------------------------------
__global__ void k3_cross(const float* __restrict__ x) {
    const int b = blockIdx.x;
    const int tid = threadIdx.x;
    __shared__ float cq[SS], ca[SS], cn[SS];
    for (int s = tid; s < SS; s += blockDim.x) {
        cq[s] = g_mask[0][b * SS + s] * g_alpha[0][b * SS + s];
        ca[s] = g_mask[1][b * SS + s] * g_alpha[1][b * SS + s];
        cn[s] = g_mask[2][b * SS + s] * g_alpha[2][b * SS + s];
    }
    __syncthreads();
    float dq = g_msum[1][b] + g_msum[2][b] + AVG_EPS_;
    float da = g_msum[0][b] + g_msum[2][b] + AVG_EPS_;
    float dn = g_msum[0][b] + g_msum[1][b] + AVG_EPS_;
    const float* xb = x + (size_t)b * SS * HH;
    for (int h = tid; h < HH; h += blockDim.x) {
        float aq = 0.f, aa = 0.f, an = 0.f;
        for (int s = 0; s < SS; s++) {
            float v = xb[(size_t)s * HH + h];
            aq = fmaf(cq[s], v, aq);
            aa = fmaf(ca[s], v, aa);
            an = fmaf(cn[s], v, an);
        }
        g_cross[0][b * HH + h] = aq / dq;
        g_cross[1][b * HH + h] = aa / da;
        g_cross[2][b * HH + h] = an / dn;
    }
}

// ---------------------------------------------------------------------------
// Kernel 4: per-batch cosine logits; also write q/a/n_output rows.
// ---------------------------------------------------------------------------
__global__ void k4_logits(float* __restrict__ out) {
    const int b = blockIdx.x;
    const int tid = threadIdx.x;
    float p[9];
    #pragma unroll
    for (int k = 0; k < 9; k++) p[k] = 0.f;
    for (int h = tid; h < HH; h += blockDim.x) {
        #pragma unroll
        for (int m = 0; m < 3; m++) {
            float sv = g_self[m][b * HH + h];
            float cv = g_cross[m][b * HH + h];
            p[m * 3 + 0] = fmaf(sv, cv, p[m * 3 + 0]);
            p[m * 3 + 1] = fmaf(sv, sv, p[m * 3 + 1]);
            p[m * 3 + 2] = fmaf(cv, cv, p[m * 3 + 2]);
        }
    }
    #pragma unroll
    for (int k = 0; k < 9; k++)
        #pragma unroll
        for (int o = 16; o > 0; o >>= 1)
            p[k] += __shfl_down_sync(0xffffffffu, p[k], o);
    __shared__ float red[9][8];
    if ((tid & 31) == 0) {
        int w = tid >> 5;
        #pragma unroll
        for (int k = 0; k < 9; k++) red[k][w] = p[k];
    }
    __syncthreads();
    if (tid == 0) {
        #pragma unroll
        for (int m = 0; m < 3; m++) {
            float dot = 0.f, n1 = 0.f, n2 = 0.f;
            for (int w = 0; w < 8; w++) {
                dot += red[m * 3 + 0][w];
                n1  += red[m * 3 + 1][w];
                n2  += red[m * 3 + 2][w];
            }
            float nx = fmaxf(sqrtf(n1), COS_EPS_);
            float ny = fmaxf(sqrtf(n2), COS_EPS_);
            float c = dot / (nx * ny);
            g_logits[m][b] = (c == 1.0f) ? __int_as_float(0x7fc00000) : c / TEMP_;
        }
    }
    if (b % SN == 0) {
        int g = b / SN;
        for (int h = tid; h < HH; h += blockDim.x) {
            out[1 + 0 * NG * HH + g * HH + h] = g_self[0][b * HH + h];
            out[1 + 1 * NG * HH + g * HH + h] = g_self[1][b * HH + h];
            out[1 + 2 * NG * HH + g * HH + h] = g_self[2][b * HH + h];
        }
    }
}

// ---------------------------------------------------------------------------
// Kernel 5: log-softmax + nanmean loss (tiny, single thread).
// ---------------------------------------------------------------------------
__global__ void k5_loss(const float* __restrict__ labels, float* __restrict__ out) {
    if (threadIdx.x != 0 || blockIdx.x != 0) return;
    float losses[3];
    for (int m = 0; m < 3; m++) {
        float sum = 0.f;
        int cnt = 0;
        for (int g = 0; g < NG; g++) {
            float l[SN];
            bool bad = false;
            for (int j = 0; j < SN; j++) {
                l[j] = g_logits[m][g * SN + j];
                if (isnan(l[j])) bad = true;
            }
            if (bad) continue;  // whole row becomes NaN after log_softmax -> excluded
            float mx = l[0];
            for (int j = 1; j < SN; j++) mx = fmaxf(mx, l[j]);
            float se = 0.f;
            for (int j = 0; j < SN; j++) se += expf(l[j] - mx);
            float lse = mx + logf(se);
            for (int j = 0; j < SN; j++) sum += (l[j] - lse) * labels[g * SN + j];
            cnt += SN;
        }
        losses[m] = -(sum / (float)cnt);  // cnt==0 -> NaN, matches nanmean of empty
    }
    out[0] = (losses[1] + losses[0] + losses[2]) / 3.0f;  // (a + q + n)/3
}

// ---------------------------------------------------------------------------
extern "C" void kernel_launch(void* const* d_in, const int* in_sizes, int n_in,
                              void* d_out, int out_size) {
    const float* x      = (const float*)d_in[0];  // self_output (72,512,768)
    const float* am     = (const float*)d_in[1];  // attention_mask (72,512)
    const float* labels = (const float*)d_in[2];  // labels (8,9)
    const int*   qa     = (const int*)d_in[3];    // qa_ids (72,512)
    const int*   turn   = (const int*)d_in[4];    // turn_ids (72,512)
    float* out = (float*)d_out;

    k1_prep<<<NB, 256>>>(x, am, qa);
    k2_gram<<<dim3(8, 8, NB), 256>>>(x, turn);
    k3_cross<<<NB, 256>>>(x);
    k4_logits<<<NB, 256>>>(out);
    k5_loss<<<1, 32>>>(labels, out);
}

// round 2
// speedup vs baseline: 1.6231x; 1.6231x over previous
#include <cuda_runtime.h>
#include <math.h>

namespace {
constexpr int NB = 72;      // batch = G * SAMPLE_NUMS
constexpr int SS = 512;
constexpr int HH = 768;
constexpr int NG = 8;
constexpr int SN = 9;
constexpr float TEMP_ = 0.07f;
constexpr float AVG_EPS_ = 1e-6f;
constexpr float COS_EPS_ = 1e-8f;
constexpr int VR = 2;
}

// Scratch (no allocations allowed)
__device__ float g_mask[3][NB * SS];   // mq, ma, mn
__device__ float g_msum[3][NB];
__device__ float g_self[3][NB * HH];
__device__ float g_alpha[3][NB * SS];
__device__ float g_cross[3][NB * HH];
__device__ float g_logits[3][NB];

// ---------------------------------------------------------------------------
// Kernel 0: per-batch masks + mask sums; zero alpha. (tiny)
// ---------------------------------------------------------------------------
__global__ void k0_masks(const float* __restrict__ am,
                         const int* __restrict__ qa) {
    const int b = blockIdx.x;
    const int tid = threadIdx.x;
    __shared__ float red[3][8];

    float pq = 0.f, pa = 0.f, pn = 0.f;
    for (int s = tid; s < SS; s += blockDim.x) {
        int q = qa[b * SS + s];
        float a = am[b * SS + s];
        float mq = (q == 1 || q == 2) ? a : 0.f;
        float ma = (q == 0 || q == 2) ? a : 0.f;
        float mn = (q == 3) ? a : 0.f;
        g_mask[0][b * SS + s] = mq;
        g_mask[1][b * SS + s] = ma;
        g_mask[2][b * SS + s] = mn;
        g_alpha[0][b * SS + s] = 0.f;
        g_alpha[1][b * SS + s] = 0.f;
        g_alpha[2][b * SS + s] = 0.f;
        pq += mq; pa += ma; pn += mn;
    }
    #pragma unroll
    for (int o = 16; o > 0; o >>= 1) {
        pq += __shfl_down_sync(0xffffffffu, pq, o);
        pa += __shfl_down_sync(0xffffffffu, pa, o);
        pn += __shfl_down_sync(0xffffffffu, pn, o);
    }
    if ((tid & 31) == 0) {
        int w = tid >> 5;
        red[0][w] = pq; red[1][w] = pa; red[2][w] = pn;
    }
    __syncthreads();
    if (tid == 0) {
        int nw = blockDim.x >> 5;
        float s0 = 0.f, s1 = 0.f, s2 = 0.f;
        for (int w = 0; w < nw; w++) { s0 += red[0][w]; s1 += red[1][w]; s2 += red[2][w]; }
        g_msum[0][b] = s0; g_msum[1][b] = s1; g_msum[2][b] = s2;
    }
}

// ---------------------------------------------------------------------------
// Kernel 1: self-averages.  grid (3, NB), 256 threads, one h per thread.
// ---------------------------------------------------------------------------
__global__ void __launch_bounds__(256) k1_self(const float* __restrict__ x) {
    const int b = blockIdx.y;
    const int h = blockIdx.x * 256 + threadIdx.x;
    const int tid = threadIdx.x;
    __shared__ float smq[SS], sma[SS], smn[SS];
    for (int s = tid; s < SS; s += 256) {
        smq[s] = g_mask[0][b * SS + s];
        sma[s] = g_mask[1][b * SS + s];
        smn[s] = g_mask[2][b * SS + s];
    }
    __syncthreads();
    const float* xb = x + (size_t)b * SS * HH + h;
    float aq = 0.f, aa = 0.f, an = 0.f;
    #pragma unroll 4
    for (int s = 0; s < SS; s++) {
        float v = xb[(size_t)s * HH];
        aq = fmaf(smq[s], v, aq);
        aa = fmaf(sma[s], v, aa);
        an = fmaf(smn[s], v, an);
    }
    g_self[0][b * HH + h] = aq / (g_msum[0][b] + AVG_EPS_);
    g_self[1][b * HH + h] = aa / (g_msum[1][b] + AVG_EPS_);
    g_self[2][b * HH + h] = an / (g_msum[2][b] + AVG_EPS_);
}

// ---------------------------------------------------------------------------
// Kernel 2: banded symmetric Gram + alpha accumulation.
// 64x64 tiles, upper triangle only, double-buffered smem + reg prefetch.
// ---------------------------------------------------------------------------
__global__ void __launch_bounds__(256) k2_gram(const float* __restrict__ x,
                                               const int* __restrict__ turn) {
    const int b = blockIdx.z;
    const int I = blockIdx.y, J = blockIdx.x;
    if (J < I) return;
    const int s0 = I * 64, t0 = J * 64;
    const int* tb = turn + b * SS;
    if (tb[t0] - tb[s0 + 63] > VR) return;   // sorted turns => whole tile out of band
    const bool diag = (I == J);
    const int tid = threadIdx.x;
    const int tx = tid & 15, ty = tid >> 4;

    __shared__ __align__(16) float As[2][32][68];
    __shared__ __align__(16) float Bs[2][32][68];
    __shared__ float sW[2][3][64];
    __shared__ float sM[2][3][64];
    __shared__ int   sT[2][64];
    __shared__ float accT[3][64];
    __shared__ float accS[3][64];

    if (tid < 128) {
        int side = tid >> 6, i = tid & 63;
        int tok = (side ? t0 : s0) + i;
        float mq = g_mask[0][b * SS + tok];
        float ma = g_mask[1][b * SS + tok];
        float mn = g_mask[2][b * SS + tok];
        sM[side][0][i] = mq; sM[side][1][i] = ma; sM[side][2][i] = mn;
        sW[side][0][i] = ma + mn;
        sW[side][1][i] = mq + mn;
        sW[side][2][i] = mq + ma;
        sT[side][i] = tb[tok];
    }
    if (tid < 64) {
        #pragma unroll
        for (int m = 0; m < 3; m++) { accT[m][tid] = 0.f; accS[m][tid] = 0.f; }
    }

    float acc[4][4];
    #pragma unroll
    for (int i = 0; i < 4; i++)
        #pragma unroll
        for (int j = 0; j < 4; j++) acc[i][j] = 0.f;

    const float4* xa  = (const float4*)(x + ((size_t)b * SS + s0) * HH);
    const float4* xbp = (const float4*)(x + ((size_t)b * SS + t0) * HH);
    const int row0 = (tid * 2)     >> 3, c40 = (tid * 2)     & 7;  // lane->(i,c4) for l=0
    const int row1 = (tid * 2 + 1) >> 3, c41 = (tid * 2 + 1) & 7;

    // NOTE: layout per l: idx = tid + l*256  =>  i = idx>>3, c4 = idx&7
    auto gidx_i  = [&](int l) { int idx = tid + l * 256; return idx >> 3; };
    auto gidx_c4 = [&](int l) { int idx = tid + l * 256; return idx & 7; };
    (void)row0; (void)row1; (void)c40; (void)c41;

    float4 pa[2], pb[2];
    #pragma unroll
    for (int l = 0; l < 2; l++) {
        int i = gidx_i(l), c4 = gidx_c4(l);
        pa[l] = xa [(size_t)i * (HH / 4) + c4];
        pb[l] = xbp[(size_t)i * (HH / 4) + c4];
    }
    #pragma unroll
    for (int l = 0; l < 2; l++) {
        int i = gidx_i(l), c4 = gidx_c4(l);
        As[0][4 * c4 + 0][i] = pa[l].x; As[0][4 * c4 + 1][i] = pa[l].y;
        As[0][4 * c4 + 2][i] = pa[l].z; As[0][4 * c4 + 3][i] = pa[l].w;
        Bs[0][4 * c4 + 0][i] = pb[l].x; Bs[0][4 * c4 + 1][i] = pb[l].y;
        Bs[0][4 * c4 + 2][i] = pb[l].z; Bs[0][4 * c4 + 3][i] = pb[l].w;
    }
    __syncthreads();

    constexpr int KSTEPS = HH / 32;  // 24
    for (int step = 0; step < KSTEPS; step++) {
        const int cur = step & 1;
        const int nxt = step + 1;
        if (nxt < KSTEPS) {
            #pragma unroll
            for (int l = 0; l < 2; l++) {
                int i = gidx_i(l), c4 = gidx_c4(l);
                pa[l] = xa [(size_t)i * (HH / 4) + nxt * 8 + c4];
                pb[l] = xbp[(size_t)i * (HH / 4) + nxt * 8 + c4];
            }
        }
        #pragma unroll
        for (int kk = 0; kk < 32; kk++) {
            float4 a  = *(const float4*)&As[cur][kk][4 * ty];
            float4 bv = *(const float4*)&Bs[cur][kk][4 * tx];
            acc[0][0] = fmaf(a.x, bv.x, acc[0][0]); acc[0][1] = fmaf(a.x, bv.y, acc[0][1]);
            acc[0][2] = fmaf(a.x, bv.z, acc[0][2]); acc[0][3] = fmaf(a.x, bv.w, acc[0][3]);
            acc[1][0] = fmaf(a.y, bv.x, acc[1][0]); acc[1][1] = fmaf(a.y, bv.y, acc[1][1]);
            acc[1][2] = fmaf(a.y, bv.z, acc[1][2]); acc[1][3] = fmaf(a.y, bv.w, acc[1][3]);
            acc[2][0] = fmaf(a.z, bv.x, acc[2][0]); acc[2][1] = fmaf(a.z, bv.y, acc[2][1]);
            acc[2][2] = fmaf(a.z, bv.z, acc[2][2]); acc[2][3] = fmaf(a.z, bv.w, acc[2][3]);
            acc[3][0] = fmaf(a.w, bv.x, acc[3][0]); acc[3][1] = fmaf(a.w, bv.y, acc[3][1]);
            acc[3][2] = fmaf(a.w, bv.z, acc[3][2]); acc[3][3] = fmaf(a.w, bv.w, acc[3][3]);
        }
        if (nxt < KSTEPS) {
            const int nb_ = nxt & 1;
            #pragma unroll
            for (int l = 0; l < 2; l++) {
                int i = gidx_i(l), c4 = gidx_c4(l);
                As[nb_][4 * c4 + 0][i] = pa[l].x; As[nb_][4 * c4 + 1][i] = pa[l].y;
                As[nb_][4 * c4 + 2][i] = pa[l].z; As[nb_][4 * c4 + 3][i] = pa[l].w;
                Bs[nb_][4 * c4 + 0][i] = pb[l].x; Bs[nb_][4 * c4 + 1][i] = pb[l].y;
                Bs[nb_][4 * c4 + 2][i] = pb[l].z; Bs[nb_][4 * c4 + 3][i] = pb[l].w;
            }
        }
        __syncthreads();
    }

    float cq[4], ca_[4], cn_[4], dq[4], da_[4], dn_[4];
    #pragma unroll
    for (int j = 0; j < 4; j++) { cq[j]=0.f; ca_[j]=0.f; cn_[j]=0.f; dq[j]=0.f; da_[j]=0.f; dn_[j]=0.f; }

    #pragma unroll
    for (int di = 0; di < 4; di++) {
        int sl = 4 * ty + di;
        int ts_ = sT[0][sl];
        float mqs = sM[0][0][sl], mas = sM[0][1][sl], mns = sM[0][2][sl];
        float wqs = sW[0][0][sl], was = sW[0][1][sl], wns = sW[0][2][sl];
        #pragma unroll
        for (int dj = 0; dj < 4; dj++) {
            int tl = 4 * tx + dj;
            int dt = sT[1][tl] - ts_;
            if (dt < -VR || dt > VR) continue;
            float wqt = sW[1][0][tl], wat = sW[1][1][tl], wnt = sW[1][2][tl];
            float coef = mqs * wqt + mas * wat + mns * wnt;
            float base = coef * acc[di][dj];
            cq[dj]  = fmaf(wqs, base, cq[dj]);
            ca_[dj] = fmaf(was, base, ca_[dj]);
            cn_[dj] = fmaf(wns, base, cn_[dj]);
            dq[di]  = fmaf(wqt, base, dq[di]);
            da_[di] = fmaf(wat, base, da_[di]);
            dn_[di] = fmaf(wnt, base, dn_[di]);
        }
    }
    #pragma unroll
    for (int dj = 0; dj < 4; dj++) {
        int tl = 4 * tx + dj;
        if (cq[dj]  != 0.f) atomicAdd(&accT[0][tl], cq[dj]);
        if (ca_[dj] != 0.f) atomicAdd(&accT[1][tl], ca_[dj]);
        if (cn_[dj] != 0.f) atomicAdd(&accT[2][tl], cn_[dj]);
    }
    if (!diag) {
        #pragma unroll
        for (int di = 0; di < 4; di++) {
            int sl = 4 * ty + di;
            if (dq[di]  != 0.f) atomicAdd(&accS[0][sl], dq[di]);
            if (da_[di] != 0.f) atomicAdd(&accS[1][sl], da_[di]);
            if (dn_[di] != 0.f) atomicAdd(&accS[2][sl], dn_[di]);
        }
    }
    __syncthreads();
    if (tid < 64) {
        #pragma unroll
        for (int m = 0; m < 3; m++) {
            float v = accT[m][tid];
            if (v != 0.f) atomicAdd(&g_alpha[m][b * SS + t0 + tid], v);
            if (!diag) {
                float w = accS[m][tid];
                if (w != 0.f) atomicAdd(&g_alpha[m][b * SS + s0 + tid], w);
            }
        }
    }
}

// ---------------------------------------------------------------------------
// Kernel 3: cross vectors.  grid (3, NB), one h per thread.
// ---------------------------------------------------------------------------
__global__ void __launch_bounds__(256) k3_cross(const float* __restrict__ x) {
    const int b = blockIdx.y;
    const int h = blockIdx.x * 256 + threadIdx.x;
    const int tid = threadIdx.x;
    __shared__ float cq[SS], ca[SS], cn[SS];
    for (int s = tid; s < SS; s += 256) {
        cq[s] = g_mask[0][b * SS + s] * g_alpha[0][b * SS + s];
        ca[s] = g_mask[1][b * SS + s] * g_alpha[1][b * SS + s];
        cn[s] = g_mask[2][b * SS + s] * g_alpha[2][b * SS + s];
    }
    __syncthreads();
    float dq = g_msum[1][b] + g_msum[2][b] + AVG_EPS_;
    float da = g_msum[0][b] + g_msum[2][b] + AVG_EPS_;
    float dn = g_msum[0][b] + g_msum[1][b] + AVG_EPS_;
    const float* xb = x + (size_t)b * SS * HH + h;
    float aq = 0.f, aa = 0.f, an = 0.f;
    #pragma unroll 4
    for (int s = 0; s < SS; s++) {
        float v = xb[(size_t)s * HH];
        aq = fmaf(cq[s], v, aq);
        aa = fmaf(ca[s], v, aa);
        an = fmaf(cn[s], v, an);
    }
    g_cross[0][b * HH + h] = aq / dq;
    g_cross[1][b * HH + h] = aa / da;
    g_cross[2][b * HH + h] = an / dn;
}

// ---------------------------------------------------------------------------
// Kernel 4: per-batch cosine logits; also write q/a/n_output rows.
// ---------------------------------------------------------------------------
__global__ void k4_logits(float* __restrict__ out) {
    const int b = blockIdx.x;
    const int tid = threadIdx.x;
    float p[9];
    #pragma unroll
    for (int k = 0; k < 9; k++) p[k] = 0.f;
    for (int h = tid; h < HH; h += blockDim.x) {
        #pragma unroll
        for (int m = 0; m < 3; m++) {
            float sv = g_self[m][b * HH + h];
            float cv = g_cross[m][b * HH + h];
            p[m * 3 + 0] = fmaf(sv, cv, p[m * 3 + 0]);
            p[m * 3 + 1] = fmaf(sv, sv, p[m * 3 + 1]);
            p[m * 3 + 2] = fmaf(cv, cv, p[m * 3 + 2]);
        }
    }
    #pragma unroll
    for (int k = 0; k < 9; k++)
        #pragma unroll
        for (int o = 16; o > 0; o >>= 1)
            p[k] += __shfl_down_sync(0xffffffffu, p[k], o);
    __shared__ float red[9][8];
    if ((tid & 31) == 0) {
        int w = tid >> 5;
        #pragma unroll
        for (int k = 0; k < 9; k++) red[k][w] = p[k];
    }
    __syncthreads();
    if (tid == 0) {
        #pragma unroll
        for (int m = 0; m < 3; m++) {
            float dot = 0.f, n1 = 0.f, n2 = 0.f;
            for (int w = 0; w < 8; w++) {
                dot += red[m * 3 + 0][w];
                n1  += red[m * 3 + 1][w];
                n2  += red[m * 3 + 2][w];
            }
            float nx = fmaxf(sqrtf(n1), COS_EPS_);
            float ny = fmaxf(sqrtf(n2), COS_EPS_);
            float c = dot / (nx * ny);
            g_logits[m][b] = (c == 1.0f) ? __int_as_float(0x7fc00000) : c / TEMP_;
        }
    }
    if (b % SN == 0) {
        int g = b / SN;
        for (int h = tid; h < HH; h += blockDim.x) {
            out[1 + 0 * NG * HH + g * HH + h] = g_self[0][b * HH + h];
            out[1 + 1 * NG * HH + g * HH + h] = g_self[1][b * HH + h];
            out[1 + 2 * NG * HH + g * HH + h] = g_self[2][b * HH + h];
        }
    }
}

// ---------------------------------------------------------------------------
// Kernel 5: log-softmax + nanmean loss (tiny).
// ---------------------------------------------------------------------------
__global__ void k5_loss(const float* __restrict__ labels, float* __restrict__ out) {
    if (threadIdx.x != 0 || blockIdx.x != 0) return;
    float losses[3];
    for (int m = 0; m < 3; m++) {
        float sum = 0.f;
        int cnt = 0;
        for (int g = 0; g < NG; g++) {
            float l[SN];
            bool bad = false;
            for (int j = 0; j < SN; j++) {
                l[j] = g_logits[m][g * SN + j];
                if (isnan(l[j])) bad = true;
            }
            if (bad) continue;
            float mx = l[0];
            for (int j = 1; j < SN; j++) mx = fmaxf(mx, l[j]);
            float se = 0.f;
            for (int j = 0; j < SN; j++) se += expf(l[j] - mx);
            float lse = mx + logf(se);
            for (int j = 0; j < SN; j++) sum += (l[j] - lse) * labels[g * SN + j];
            cnt += SN;
        }
        losses[m] = -(sum / (float)cnt);
    }
    out[0] = (losses[1] + losses[0] + losses[2]) / 3.0f;
}

// ---------------------------------------------------------------------------
extern "C" void kernel_launch(void* const* d_in, const int* in_sizes, int n_in,
                              void* d_out, int out_size) {
    const float* x      = (const float*)d_in[0];
    const float* am     = (const float*)d_in[1];
    const float* labels = (const float*)d_in[2];
    const int*   qa     = (const int*)d_in[3];
    const int*   turn   = (const int*)d_in[4];
    float* out = (float*)d_out;

    k0_masks<<<NB, 256>>>(am, qa);
    k1_self<<<dim3(3, NB), 256>>>(x);
    k2_gram<<<dim3(8, 8, NB), 256>>>(x, turn);
    k3_cross<<<dim3(3, NB), 256>>>(x);
    k4_logits<<<NB, 256>>>(out);
    k5_loss<<<1, 32>>>(labels, out);
}

// round 3
// speedup vs baseline: 2.2594x; 1.3920x over previous
#include <cuda_runtime.h>
#include <math.h>

namespace {
constexpr int NB = 72;
constexpr int SS = 512;
constexpr int HH = 768;
constexpr int NG = 8;
constexpr int SN = 9;
constexpr float TEMP_ = 0.07f;
constexpr float AVG_EPS_ = 1e-6f;
constexpr float COS_EPS_ = 1e-8f;
constexpr int VR = 2;
constexpr int SPLITS = 4;           // s-split for fused streaming pass
constexpr int SCHUNK = SS / SPLITS; // 128
}

// Scratch (no allocations allowed)
__device__ float g_mask[3][NB * SS];
__device__ float g_msum[3][NB];
__device__ float g_self[3][NB * HH];
__device__ float g_alpha[3][NB * SS];
__device__ float g_cross[3][NB * HH];
__device__ float g_logits[3][NB];

// packed f32x2 fma: d = a*b + d  (two independent fp32 FMAs)
__device__ __forceinline__ void ffma2(float2& d, const float2& a, const float2& b) {
    unsigned long long& dd = reinterpret_cast<unsigned long long&>(d);
    const unsigned long long& aa = reinterpret_cast<const unsigned long long&>(a);
    const unsigned long long& bb = reinterpret_cast<const unsigned long long&>(b);
    asm("fma.rn.f32x2 %0, %1, %2, %0;" : "+l"(dd) : "l"(aa), "l"(bb));
}

// ---------------------------------------------------------------------------
// Kernel 0: masks + mask sums; zero alpha, self, cross.
// ---------------------------------------------------------------------------
__global__ void k0_masks(const float* __restrict__ am,
                         const int* __restrict__ qa) {
    const int b = blockIdx.x;
    const int tid = threadIdx.x;
    __shared__ float red[3][8];

    float pq = 0.f, pa = 0.f, pn = 0.f;
    for (int s = tid; s < SS; s += blockDim.x) {
        int q = qa[b * SS + s];
        float a = am[b * SS + s];
        float mq = (q == 1 || q == 2) ? a : 0.f;
        float ma = (q == 0 || q == 2) ? a : 0.f;
        float mn = (q == 3) ? a : 0.f;
        g_mask[0][b * SS + s] = mq;
        g_mask[1][b * SS + s] = ma;
        g_mask[2][b * SS + s] = mn;
        g_alpha[0][b * SS + s] = 0.f;
        g_alpha[1][b * SS + s] = 0.f;
        g_alpha[2][b * SS + s] = 0.f;
        pq += mq; pa += ma; pn += mn;
    }
    for (int h = tid; h < HH; h += blockDim.x) {
        #pragma unroll
        for (int m = 0; m < 3; m++) {
            g_self[m][b * HH + h] = 0.f;
            g_cross[m][b * HH + h] = 0.f;
        }
    }
    #pragma unroll
    for (int o = 16; o > 0; o >>= 1) {
        pq += __shfl_down_sync(0xffffffffu, pq, o);
        pa += __shfl_down_sync(0xffffffffu, pa, o);
        pn += __shfl_down_sync(0xffffffffu, pn, o);
    }
    if ((tid & 31) == 0) {
        int w = tid >> 5;
        red[0][w] = pq; red[1][w] = pa; red[2][w] = pn;
    }
    __syncthreads();
    if (tid == 0) {
        int nw = blockDim.x >> 5;
        float s0 = 0.f, s1 = 0.f, s2 = 0.f;
        for (int w = 0; w < nw; w++) { s0 += red[0][w]; s1 += red[1][w]; s2 += red[2][w]; }
        g_msum[0][b] = s0; g_msum[1][b] = s1; g_msum[2][b] = s2;
    }
}

// ---------------------------------------------------------------------------
// Kernel 2: banded symmetric Gram + alpha accumulation (FFMA2 inner loop).
// ---------------------------------------------------------------------------
__global__ void __launch_bounds__(256) k2_gram(const float* __restrict__ x,
                                               const int* __restrict__ turn) {
    const int b = blockIdx.z;
    const int I = blockIdx.y, J = blockIdx.x;
    if (J < I) return;
    const int s0 = I * 64, t0 = J * 64;
    const int* tb = turn + b * SS;
    if (tb[t0] - tb[s0 + 63] > VR) return;
    const bool diag = (I == J);
    const int tid = threadIdx.x;
    const int tx = tid & 15, ty = tid >> 4;

    __shared__ __align__(16) float As[2][32][68];
    __shared__ __align__(16) float Bs[2][32][68];
    __shared__ float sW[2][3][64];
    __shared__ float sM[2][3][64];
    __shared__ int   sT[2][64];
    __shared__ float accT[3][64];
    __shared__ float accS[3][64];

    if (tid < 128) {
        int side = tid >> 6, i = tid & 63;
        int tok = (side ? t0 : s0) + i;
        float mq = g_mask[0][b * SS + tok];
        float ma = g_mask[1][b * SS + tok];
        float mn = g_mask[2][b * SS + tok];
        sM[side][0][i] = mq; sM[side][1][i] = ma; sM[side][2][i] = mn;
        sW[side][0][i] = ma + mn;
        sW[side][1][i] = mq + mn;
        sW[side][2][i] = mq + ma;
        sT[side][i] = tb[tok];
    }
    if (tid < 64) {
        #pragma unroll
        for (int m = 0; m < 3; m++) { accT[m][tid] = 0.f; accS[m][tid] = 0.f; }
    }

    // acc2[ip][j]: rows (4*ty + 2*ip, 4*ty + 2*ip + 1) x col (4*tx + j)
    float2 acc2[2][4];
    #pragma unroll
    for (int ip = 0; ip < 2; ip++)
        #pragma unroll
        for (int j = 0; j < 4; j++) acc2[ip][j] = make_float2(0.f, 0.f);

    const float4* xa  = (const float4*)(x + ((size_t)b * SS + s0) * HH);
    const float4* xbp = (const float4*)(x + ((size_t)b * SS + t0) * HH);
    auto gidx_i  = [&](int l) { int idx = tid + l * 256; return idx >> 3; };
    auto gidx_c4 = [&](int l) { int idx = tid + l * 256; return idx & 7; };

    float4 pa[2], pb[2];
    #pragma unroll
    for (int l = 0; l < 2; l++) {
        int i = gidx_i(l), c4 = gidx_c4(l);
        pa[l] = xa [(size_t)i * (HH / 4) + c4];
        pb[l] = xbp[(size_t)i * (HH / 4) + c4];
    }
    #pragma unroll
    for (int l = 0; l < 2; l++) {
        int i = gidx_i(l), c4 = gidx_c4(l);
        As[0][4 * c4 + 0][i] = pa[l].x; As[0][4 * c4 + 1][i] = pa[l].y;
        As[0][4 * c4 + 2][i] = pa[l].z; As[0][4 * c4 + 3][i] = pa[l].w;
        Bs[0][4 * c4 + 0][i] = pb[l].x; Bs[0][4 * c4 + 1][i] = pb[l].y;
        Bs[0][4 * c4 + 2][i] = pb[l].z; Bs[0][4 * c4 + 3][i] = pb[l].w;
    }
    __syncthreads();

    constexpr int KSTEPS = HH / 32;
    for (int step = 0; step < KSTEPS; step++) {
        const int cur = step & 1;
        const int nxt = step + 1;
        if (nxt < KSTEPS) {
            #pragma unroll
            for (int l = 0; l < 2; l++) {
                int i = gidx_i(l), c4 = gidx_c4(l);
                pa[l] = xa [(size_t)i * (HH / 4) + nxt * 8 + c4];
                pb[l] = xbp[(size_t)i * (HH / 4) + nxt * 8 + c4];
            }
        }
        #pragma unroll
        for (int kk = 0; kk < 32; kk++) {
            float4 a  = *(const float4*)&As[cur][kk][4 * ty];
            float4 bv = *(const float4*)&Bs[cur][kk][4 * tx];
            float2 ap0 = make_float2(a.x, a.y);
            float2 ap1 = make_float2(a.z, a.w);
            float2 b0 = make_float2(bv.x, bv.x);
            float2 b1 = make_float2(bv.y, bv.y);
            float2 b2 = make_float2(bv.z, bv.z);
            float2 b3 = make_float2(bv.w, bv.w);
            ffma2(acc2[0][0], ap0, b0); ffma2(acc2[0][1], ap0, b1);
            ffma2(acc2[0][2], ap0, b2); ffma2(acc2[0][3], ap0, b3);
            ffma2(acc2[1][0], ap1, b0); ffma2(acc2[1][1], ap1, b1);
            ffma2(acc2[1][2], ap1, b2); ffma2(acc2[1][3], ap1, b3);
        }
        if (nxt < KSTEPS) {
            const int nb_ = nxt & 1;
            #pragma unroll
            for (int l = 0; l < 2; l++) {
                int i = gidx_i(l), c4 = gidx_c4(l);
                As[nb_][4 * c4 + 0][i] = pa[l].x; As[nb_][4 * c4 + 1][i] = pa[l].y;
                As[nb_][4 * c4 + 2][i] = pa[l].z; As[nb_][4 * c4 + 3][i] = pa[l].w;
                Bs[nb_][4 * c4 + 0][i] = pb[l].x; Bs[nb_][4 * c4 + 1][i] = pb[l].y;
                Bs[nb_][4 * c4 + 2][i] = pb[l].z; Bs[nb_][4 * c4 + 3][i] = pb[l].w;
            }
        }
        __syncthreads();
    }

    // unpack: acc[di][dj], di = 2*ip + (x:0, y:1)
    float acc[4][4];
    #pragma unroll
    for (int ip = 0; ip < 2; ip++)
        #pragma unroll
        for (int j = 0; j < 4; j++) {
            acc[2 * ip + 0][j] = acc2[ip][j].x;
            acc[2 * ip + 1][j] = acc2[ip][j].y;
        }

    float cq[4], ca_[4], cn_[4], dq[4], da_[4], dn_[4];
    #pragma unroll
    for (int j = 0; j < 4; j++) { cq[j]=0.f; ca_[j]=0.f; cn_[j]=0.f; dq[j]=0.f; da_[j]=0.f; dn_[j]=0.f; }

    #pragma unroll
    for (int di = 0; di < 4; di++) {
        int sl = 4 * ty + di;
        int ts_ = sT[0][sl];
        float mqs = sM[0][0][sl], mas = sM[0][1][sl], mns = sM[0][2][sl];
        float wqs = sW[0][0][sl], was = sW[0][1][sl], wns = sW[0][2][sl];
        #pragma unroll
        for (int dj = 0; dj < 4; dj++) {
            int tl = 4 * tx + dj;
            int dt = sT[1][tl] - ts_;
            if (dt < -VR || dt > VR) continue;
            float wqt = sW[1][0][tl], wat = sW[1][1][tl], wnt = sW[1][2][tl];
            float coef = mqs * wqt + mas * wat + mns * wnt;
            float base = coef * acc[di][dj];
            cq[dj]  = fmaf(wqs, base, cq[dj]);
            ca_[dj] = fmaf(was, base, ca_[dj]);
            cn_[dj] = fmaf(wns, base, cn_[dj]);
            dq[di]  = fmaf(wqt, base, dq[di]);
            da_[di] = fmaf(wat, base, da_[di]);
            dn_[di] = fmaf(wnt, base, dn_[di]);
        }
    }
    #pragma unroll
    for (int dj = 0; dj < 4; dj++) {
        int tl = 4 * tx + dj;
        if (cq[dj]  != 0.f) atomicAdd(&accT[0][tl], cq[dj]);
        if (ca_[dj] != 0.f) atomicAdd(&accT[1][tl], ca_[dj]);
        if (cn_[dj] != 0.f) atomicAdd(&accT[2][tl], cn_[dj]);
    }
    if (!diag) {
        #pragma unroll
        for (int di = 0; di < 4; di++) {
            int sl = 4 * ty + di;
            if (dq[di]  != 0.f) atomicAdd(&accS[0][sl], dq[di]);
            if (da_[di] != 0.f) atomicAdd(&accS[1][sl], da_[di]);
            if (dn_[di] != 0.f) atomicAdd(&accS[2][sl], dn_[di]);
        }
    }
    __syncthreads();
    if (tid < 64) {
        #pragma unroll
        for (int m = 0; m < 3; m++) {
            float v = accT[m][tid];
            if (v != 0.f) atomicAdd(&g_alpha[m][b * SS + t0 + tid], v);
            if (!diag) {
                float w = accS[m][tid];
                if (w != 0.f) atomicAdd(&g_alpha[m][b * SS + s0 + tid], w);
            }
        }
    }
}

// ---------------------------------------------------------------------------
// Kernel 3: FUSED self + cross streaming pass, s-split with atomics.
// grid (3 hblk, NB, SPLITS). Partials are pre-scaled by 1/denominator.
// ---------------------------------------------------------------------------
__global__ void __launch_bounds__(256) k3_fused(const float* __restrict__ x) {
    const int b = blockIdx.y;
    const int h = blockIdx.x * 256 + threadIdx.x;
    const int sc = blockIdx.z;
    const int sbase = sc * SCHUNK;
    const int tid = threadIdx.x;

    __shared__ float smq[SCHUNK], sma[SCHUNK], smn[SCHUNK];
    __shared__ float scq[SCHUNK], sca[SCHUNK], scn[SCHUNK];
    for (int s = tid; s < SCHUNK; s += 256) {
        int gs = b * SS + sbase + s;
        float mq = g_mask[0][gs], ma = g_mask[1][gs], mn = g_mask[2][gs];
        smq[s] = mq; sma[s] = ma; smn[s] = mn;
        scq[s] = mq * g_alpha[0][gs];
        sca[s] = ma * g_alpha[1][gs];
        scn[s] = mn * g_alpha[2][gs];
    }
    __syncthreads();

    float m0 = g_msum[0][b], m1 = g_msum[1][b], m2 = g_msum[2][b];
    float rsq = 1.f / (m0 + AVG_EPS_);
    float rsa = 1.f / (m1 + AVG_EPS_);
    float rsn = 1.f / (m2 + AVG_EPS_);
    float rcq = 1.f / (m1 + m2 + AVG_EPS_);
    float rca = 1.f / (m0 + m2 + AVG_EPS_);
    float rcn = 1.f / (m0 + m1 + AVG_EPS_);

    const float* xb = x + ((size_t)b * SS + sbase) * HH + h;
    float aq = 0.f, aa = 0.f, an = 0.f;   // self
    float bq = 0.f, ba = 0.f, bn = 0.f;   // cross
    #pragma unroll 4
    for (int s = 0; s < SCHUNK; s++) {
        float v = xb[(size_t)s * HH];
        aq = fmaf(smq[s], v, aq);
        aa = fmaf(sma[s], v, aa);
        an = fmaf(smn[s], v, an);
        bq = fmaf(scq[s], v, bq);
        ba = fmaf(sca[s], v, ba);
        bn = fmaf(scn[s], v, bn);
    }
    atomicAdd(&g_self[0][b * HH + h], aq * rsq);
    atomicAdd(&g_self[1][b * HH + h], aa * rsa);
    atomicAdd(&g_self[2][b * HH + h], an * rsn);
    atomicAdd(&g_cross[0][b * HH + h], bq * rcq);
    atomicAdd(&g_cross[1][b * HH + h], ba * rca);
    atomicAdd(&g_cross[2][b * HH + h], bn * rcn);
}

// ---------------------------------------------------------------------------
// Kernel 4: per-batch cosine logits; write q/a/n_output rows.
// ---------------------------------------------------------------------------
__global__ void k4_logits(float* __restrict__ out) {
    const int b = blockIdx.x;
    const int tid = threadIdx.x;
    float p[9];
    #pragma unroll
    for (int k = 0; k < 9; k++) p[k] = 0.f;
    for (int h = tid; h < HH; h += blockDim.x) {
        #pragma unroll
        for (int m = 0; m < 3; m++) {
            float sv = g_self[m][b * HH + h];
            float cv = g_cross[m][b * HH + h];
            p[m * 3 + 0] = fmaf(sv, cv, p[m * 3 + 0]);
            p[m * 3 + 1] = fmaf(sv, sv, p[m * 3 + 1]);
            p[m * 3 + 2] = fmaf(cv, cv, p[m * 3 + 2]);
        }
    }
    #pragma unroll
    for (int k = 0; k < 9; k++)
        #pragma unroll
        for (int o = 16; o > 0; o >>= 1)
            p[k] += __shfl_down_sync(0xffffffffu, p[k], o);
    __shared__ float red[9][8];
    if ((tid & 31) == 0) {
        int w = tid >> 5;
        #pragma unroll
        for (int k = 0; k < 9; k++) red[k][w] = p[k];
    }
    __syncthreads();
    if (tid == 0) {
        #pragma unroll
        for (int m = 0; m < 3; m++) {
            float dot = 0.f, n1 = 0.f, n2 = 0.f;
            for (int w = 0; w < 8; w++) {
                dot += red[m * 3 + 0][w];
                n1  += red[m * 3 + 1][w];
                n2  += red[m * 3 + 2][w];
            }
            float nx = fmaxf(sqrtf(n1), COS_EPS_);
            float ny = fmaxf(sqrtf(n2), COS_EPS_);
            float c = dot / (nx * ny);
            g_logits[m][b] = (c == 1.0f) ? __int_as_float(0x7fc00000) : c / TEMP_;
        }
    }
    if (b % SN == 0) {
        int g = b / SN;
        for (int h = tid; h < HH; h += blockDim.x) {
            out[1 + 0 * NG * HH + g * HH + h] = g_self[0][b * HH + h];
            out[1 + 1 * NG * HH + g * HH + h] = g_self[1][b * HH + h];
            out[1 + 2 * NG * HH + g * HH + h] = g_self[2][b * HH + h];
        }
    }
}

// ---------------------------------------------------------------------------
// Kernel 5: log-softmax + nanmean loss (tiny).
// ---------------------------------------------------------------------------
__global__ void k5_loss(const float* __restrict__ labels, float* __restrict__ out) {
    if (threadIdx.x != 0 || blockIdx.x != 0) return;
    float losses[3];
    for (int m = 0; m < 3; m++) {
        float sum = 0.f;
        int cnt = 0;
        for (int g = 0; g < NG; g++) {
            float l[SN];
            bool bad = false;
            for (int j = 0; j < SN; j++) {
                l[j] = g_logits[m][g * SN + j];
                if (isnan(l[j])) bad = true;
            }
            if (bad) continue;
            float mx = l[0];
            for (int j = 1; j < SN; j++) mx = fmaxf(mx, l[j]);
            float se = 0.f;
            for (int j = 0; j < SN; j++) se += expf(l[j] - mx);
            float lse = mx + logf(se);
            for (int j = 0; j < SN; j++) sum += (l[j] - lse) * labels[g * SN + j];
            cnt += SN;
        }
        losses[m] = -(sum / (float)cnt);
    }
    out[0] = (losses[1] + losses[0] + losses[2]) / 3.0f;
}

// ---------------------------------------------------------------------------
extern "C" void kernel_launch(void* const* d_in, const int* in_sizes, int n_in,
                              void* d_out, int out_size) {
    const float* x      = (const float*)d_in[0];
    const float* am     = (const float*)d_in[1];
    const float* labels = (const float*)d_in[2];
    const int*   qa     = (const int*)d_in[3];
    const int*   turn   = (const int*)d_in[4];
    float* out = (float*)d_out;

    k0_masks<<<NB, 256>>>(am, qa);
    k2_gram<<<dim3(8, 8, NB), 256>>>(x, turn);
    k3_fused<<<dim3(3, NB, SPLITS), 256>>>(x);
    k4_logits<<<NB, 256>>>(out);
    k5_loss<<<1, 32>>>(labels, out);
}